// round 7
// baseline (speedup 1.0000x reference)
#include <cuda_runtime.h>
#include <math.h>

// Problem constants
#define B_   4096
#define M_   65536
#define D_   64
#define CD_  32

// Tiling
#define S_       8            // M-splits (grid.y)
#define MCHUNK   (M_ / S_)    // 8192 slots per CTA
#define BT       64           // batch rows per CTA
#define MT       64           // slots per inner tile
#define NTHREADS 256

// Padded shared strides (floats) to avoid bank conflicts
#define QS 68
#define CS 36
#define KS 68
#define VS 68
#define PS 68

#define SMEM_FLOATS (BT*QS + BT*CS + MT*KS + MT*CS + MT*VS + BT*PS + MT)
#define SMEM_BYTES  (SMEM_FLOATS * 4)

// Scratch (no cudaMalloc allowed): bias + split partials
__device__ float g_bias[M_];
__device__ float g_pacc[B_ * S_ * D_];
__device__ float g_pm[B_ * S_];
__device__ float g_pl[B_ * S_];

// ---------------------------------------------------------------------------
// Kernel 1: per-slot additive bias: 0.3*exp(-0.1*(1-t)) for used slots,
// -1e9 for unused (content scores are O(10), so total stays ~-1e9 and
// exp underflows to exactly 0 after max-subtraction, matching the reference).
// ---------------------------------------------------------------------------
__global__ void bias_kernel(const float* __restrict__ ts,
                            const int* __restrict__ used) {
    int i = blockIdx.x * blockDim.x + threadIdx.x;
    if (i < M_) {
        float b = -1e9f;
        if (used[i] != 0) b = 0.3f * expf(-0.1f * (1.0f - ts[i]));
        g_bias[i] = b;
    }
}

// ---------------------------------------------------------------------------
// Kernel 2: flash-style fused scores + online softmax + P·V over an M-chunk.
// blockIdx.x -> batch tile (64 rows), blockIdx.y -> M split.
// Thread (rg, cg): rg = tid>>4 owns rows rg*4..+3 (both phases),
//                  cg = tid&15 owns score cols cg*4..+3 and out dims cg*4..+3.
// ---------------------------------------------------------------------------
__global__ __launch_bounds__(NTHREADS, 2)
void flash_kernel(const float* __restrict__ q,
                  const float* __restrict__ ctx,
                  const float* __restrict__ mk,
                  const float* __restrict__ mv,
                  const float* __restrict__ mc) {
    extern __shared__ float sm[];
    float* sQ  = sm;                 // [BT][QS]
    float* sC  = sQ  + BT * QS;      // [BT][CS]  (prescaled by 0.5)
    float* sK  = sC  + BT * CS;      // [MT][KS]
    float* sCk = sK  + MT * KS;      // [MT][CS]
    float* sV  = sCk + MT * CS;      // [MT][VS]
    float* sP  = sV  + MT * VS;      // [BT][PS]
    float* sB  = sP  + BT * PS;      // [MT]

    const int tid = threadIdx.x;
    const int rg = tid >> 4;
    const int cg = tid & 15;
    const int r0 = rg * 4;
    const int c0 = cg * 4;
    const int d0 = cg * 4;
    const int row0 = blockIdx.x * BT;
    const int m_start = blockIdx.y * MCHUNK;

    // Stage Q and 0.5*Ctx for this batch tile (reused for all 128 M-tiles)
    for (int i = tid; i < BT * D_ / 4; i += NTHREADS) {
        int e = i * 4, r = e >> 6, c = e & 63;
        *(float4*)(sQ + r * QS + c) = *(const float4*)(q + (row0 + r) * D_ + c);
    }
    for (int i = tid; i < BT * CD_ / 4; i += NTHREADS) {
        int e = i * 4, r = e >> 5, c = e & 31;
        float4 v = *(const float4*)(ctx + (row0 + r) * CD_ + c);
        v.x *= 0.5f; v.y *= 0.5f; v.z *= 0.5f; v.w *= 0.5f;
        *(float4*)(sC + r * CS + c) = v;
    }

    float acc[4][4] = {};
    float m_run[4], l_run[4];
#pragma unroll
    for (int i = 0; i < 4; i++) { m_run[i] = -1e30f; l_run[i] = 0.0f; }

    __syncthreads();

    for (int t = 0; t < MCHUNK / MT; ++t) {
        const int m0 = m_start + t * MT;

        // ---- Stage K, C, V, bias tile ----
        for (int i = tid; i < MT * D_ / 4; i += NTHREADS) {
            int e = i * 4, r = e >> 6, c = e & 63;
            *(float4*)(sK + r * KS + c) = *(const float4*)(mk + (m0 + r) * D_ + c);
            *(float4*)(sV + r * VS + c) = *(const float4*)(mv + (m0 + r) * D_ + c);
        }
        for (int i = tid; i < MT * CD_ / 4; i += NTHREADS) {
            int e = i * 4, r = e >> 5, c = e & 31;
            *(float4*)(sCk + r * CS + c) = *(const float4*)(mc + (m0 + r) * CD_ + c);
        }
        if (tid < MT) sB[tid] = g_bias[m0 + tid];
        __syncthreads();

        // ---- Scores: 4x4 micro-tile over D (Q·K) then CD (0.5*Ctx·C) ----
        float s[4][4] = {};
#pragma unroll
        for (int kk = 0; kk < D_; kk += 4) {
            float4 qa[4], kb[4];
#pragma unroll
            for (int i = 0; i < 4; i++) qa[i] = *(const float4*)(sQ + (r0 + i) * QS + kk);
#pragma unroll
            for (int j = 0; j < 4; j++) kb[j] = *(const float4*)(sK + (c0 + j) * KS + kk);
#pragma unroll
            for (int i = 0; i < 4; i++)
#pragma unroll
                for (int j = 0; j < 4; j++) {
                    s[i][j] = fmaf(qa[i].x, kb[j].x, s[i][j]);
                    s[i][j] = fmaf(qa[i].y, kb[j].y, s[i][j]);
                    s[i][j] = fmaf(qa[i].z, kb[j].z, s[i][j]);
                    s[i][j] = fmaf(qa[i].w, kb[j].w, s[i][j]);
                }
        }
#pragma unroll
        for (int kk = 0; kk < CD_; kk += 4) {
            float4 qa[4], kb[4];
#pragma unroll
            for (int i = 0; i < 4; i++) qa[i] = *(const float4*)(sC + (r0 + i) * CS + kk);
#pragma unroll
            for (int j = 0; j < 4; j++) kb[j] = *(const float4*)(sCk + (c0 + j) * CS + kk);
#pragma unroll
            for (int i = 0; i < 4; i++)
#pragma unroll
                for (int j = 0; j < 4; j++) {
                    s[i][j] = fmaf(qa[i].x, kb[j].x, s[i][j]);
                    s[i][j] = fmaf(qa[i].y, kb[j].y, s[i][j]);
                    s[i][j] = fmaf(qa[i].z, kb[j].z, s[i][j]);
                    s[i][j] = fmaf(qa[i].w, kb[j].w, s[i][j]);
                }
        }

        // ---- Bias + online softmax update (row stats across 16 cg lanes) ----
#pragma unroll
        for (int i = 0; i < 4; i++) {
#pragma unroll
            for (int j = 0; j < 4; j++) s[i][j] += sB[c0 + j];

            float mx = fmaxf(fmaxf(s[i][0], s[i][1]), fmaxf(s[i][2], s[i][3]));
#pragma unroll
            for (int off = 8; off >= 1; off >>= 1)
                mx = fmaxf(mx, __shfl_xor_sync(0xffffffffu, mx, off));

            float nm = fmaxf(m_run[i], mx);
            float alpha = __expf(m_run[i] - nm);
            float rs = 0.0f;
#pragma unroll
            for (int j = 0; j < 4; j++) {
                float p = __expf(s[i][j] - nm);
                s[i][j] = p;
                rs += p;
            }
#pragma unroll
            for (int off = 8; off >= 1; off >>= 1)
                rs += __shfl_xor_sync(0xffffffffu, rs, off);

            l_run[i] = l_run[i] * alpha + rs;
            m_run[i] = nm;
#pragma unroll
            for (int j = 0; j < 4; j++) acc[i][j] *= alpha;

            *(float4*)(sP + (r0 + i) * PS + c0) =
                make_float4(s[i][0], s[i][1], s[i][2], s[i][3]);
        }
        __syncthreads();

        // ---- P·V accumulate: rows r0..+3, out dims d0..+3 ----
#pragma unroll 4
        for (int mm = 0; mm < MT; mm += 4) {
            float4 vv[4];
#pragma unroll
            for (int u = 0; u < 4; u++)
                vv[u] = *(const float4*)(sV + (mm + u) * VS + d0);
#pragma unroll
            for (int i = 0; i < 4; i++) {
                float4 pv = *(const float4*)(sP + (r0 + i) * PS + mm);
                float pa[4] = {pv.x, pv.y, pv.z, pv.w};
#pragma unroll
                for (int u = 0; u < 4; u++) {
                    float p = pa[u];
                    acc[i][0] = fmaf(p, vv[u].x, acc[i][0]);
                    acc[i][1] = fmaf(p, vv[u].y, acc[i][1]);
                    acc[i][2] = fmaf(p, vv[u].z, acc[i][2]);
                    acc[i][3] = fmaf(p, vv[u].w, acc[i][3]);
                }
            }
        }
        __syncthreads();   // protect sK/sV/sP before next tile's loads
    }

    // ---- Write split partials ----
#pragma unroll
    for (int i = 0; i < 4; i++) {
        int brow = row0 + r0 + i;
        int pidx = brow * S_ + blockIdx.y;
        *(float4*)(g_pacc + pidx * D_ + d0) =
            make_float4(acc[i][0], acc[i][1], acc[i][2], acc[i][3]);
        if (cg == 0) {
            g_pm[pidx] = m_run[i];
            g_pl[pidx] = l_run[i];
        }
    }
}

// ---------------------------------------------------------------------------
// Kernel 3: combine S split partials per row. One warp per row, 2 dims/lane.
// ---------------------------------------------------------------------------
__global__ void combine_kernel(float* __restrict__ out) {
    int warp = threadIdx.x >> 5;
    int lane = threadIdx.x & 31;
    int row = blockIdx.x * 8 + warp;
    if (row >= B_) return;

    float pm[S_];
    float nm = -1e30f;
#pragma unroll
    for (int s = 0; s < S_; s++) {
        pm[s] = g_pm[row * S_ + s];
        nm = fmaxf(nm, pm[s]);
    }
    float den = 0.0f, n0 = 0.0f, n1 = 0.0f;
#pragma unroll
    for (int s = 0; s < S_; s++) {
        float w = __expf(pm[s] - nm);
        den += w * g_pl[row * S_ + s];
        n0  += w * g_pacc[(row * S_ + s) * D_ + lane];
        n1  += w * g_pacc[(row * S_ + s) * D_ + lane + 32];
    }
    float inv = 1.0f / den;
    out[row * D_ + lane]      = n0 * inv;
    out[row * D_ + lane + 32] = n1 * inv;
}

// ---------------------------------------------------------------------------
// Launch
// ---------------------------------------------------------------------------
extern "C" void kernel_launch(void* const* d_in, const int* in_sizes, int n_in,
                              void* d_out, int out_size) {
    const float* q   = (const float*)d_in[0];  // [B, D]
    const float* ctx = (const float*)d_in[1];  // [B, CD]
    const float* mk  = (const float*)d_in[2];  // [M, D]
    const float* mv  = (const float*)d_in[3];  // [M, D]
    const float* mc  = (const float*)d_in[4];  // [M, CD]
    const float* ts  = (const float*)d_in[5];  // [M]
    const int*   us  = (const int*)d_in[6];    // [M] bool as int32
    float* out = (float*)d_out;

    cudaFuncSetAttribute(flash_kernel,
                         cudaFuncAttributeMaxDynamicSharedMemorySize,
                         SMEM_BYTES);

    bias_kernel<<<M_ / 256, 256>>>(ts, us);
    flash_kernel<<<dim3(B_ / BT, S_), NTHREADS, SMEM_BYTES>>>(q, ctx, mk, mv, mc);
    combine_kernel<<<B_ / 8, 256>>>(out);
}

// round 8
// speedup vs baseline: 1.0005x; 1.0005x over previous
#include <cuda_runtime.h>
#include <math.h>

// Problem constants
#define B_   4096
#define M_   65536
#define D_   64
#define CD_  32

// Tiling
#define S_       8            // M-splits (grid.y)
#define MCHUNK   (M_ / S_)    // 8192 slots per CTA
#define BT       64           // batch rows per CTA
#define MT       64           // slots per inner tile
#define NTHREADS 256

// Padded shared strides (floats) to avoid bank conflicts
#define QS 68
#define CS 36
#define KS 68
#define VS 68
#define PS 68

#define SMEM_FLOATS (BT*QS + BT*CS + MT*KS + MT*CS + MT*VS + BT*PS + MT)
#define SMEM_BYTES  (SMEM_FLOATS * 4)

// Scratch (no cudaMalloc allowed): bias + split partials
__device__ float g_bias[M_];
__device__ float g_pacc[B_ * S_ * D_];
__device__ float g_pm[B_ * S_];
__device__ float g_pl[B_ * S_];

// ---------------------------------------------------------------------------
// Kernel 1: per-slot additive bias: 0.3*exp(-0.1*(1-t)) for used slots,
// -1e9 for unused (content scores are O(10), so total stays ~-1e9 and
// exp underflows to exactly 0 after max-subtraction, matching the reference).
// ---------------------------------------------------------------------------
__global__ void bias_kernel(const float* __restrict__ ts,
                            const int* __restrict__ used) {
    int i = blockIdx.x * blockDim.x + threadIdx.x;
    if (i < M_) {
        float b = -1e9f;
        if (used[i] != 0) b = 0.3f * expf(-0.1f * (1.0f - ts[i]));
        g_bias[i] = b;
    }
}

// ---------------------------------------------------------------------------
// Kernel 2: flash-style fused scores + online softmax + P·V over an M-chunk.
// blockIdx.x -> batch tile (64 rows), blockIdx.y -> M split.
// Thread (rg, cg): rg = tid>>4 owns rows rg*4..+3 (both phases),
//                  cg = tid&15 owns score cols cg*4..+3 and out dims cg*4..+3.
// ---------------------------------------------------------------------------
__global__ __launch_bounds__(NTHREADS, 2)
void flash_kernel(const float* __restrict__ q,
                  const float* __restrict__ ctx,
                  const float* __restrict__ mk,
                  const float* __restrict__ mv,
                  const float* __restrict__ mc) {
    extern __shared__ float sm[];
    float* sQ  = sm;                 // [BT][QS]
    float* sC  = sQ  + BT * QS;      // [BT][CS]  (prescaled by 0.5)
    float* sK  = sC  + BT * CS;      // [MT][KS]
    float* sCk = sK  + MT * KS;      // [MT][CS]
    float* sV  = sCk + MT * CS;      // [MT][VS]
    float* sP  = sV  + MT * VS;      // [BT][PS]
    float* sB  = sP  + BT * PS;      // [MT]

    const int tid = threadIdx.x;
    const int rg = tid >> 4;
    const int cg = tid & 15;
    const int r0 = rg * 4;
    const int c0 = cg * 4;
    const int d0 = cg * 4;
    const int row0 = blockIdx.x * BT;
    const int m_start = blockIdx.y * MCHUNK;

    // Stage Q and 0.5*Ctx for this batch tile (reused for all 128 M-tiles)
    for (int i = tid; i < BT * D_ / 4; i += NTHREADS) {
        int e = i * 4, r = e >> 6, c = e & 63;
        *(float4*)(sQ + r * QS + c) = *(const float4*)(q + (row0 + r) * D_ + c);
    }
    for (int i = tid; i < BT * CD_ / 4; i += NTHREADS) {
        int e = i * 4, r = e >> 5, c = e & 31;
        float4 v = *(const float4*)(ctx + (row0 + r) * CD_ + c);
        v.x *= 0.5f; v.y *= 0.5f; v.z *= 0.5f; v.w *= 0.5f;
        *(float4*)(sC + r * CS + c) = v;
    }

    float acc[4][4] = {};
    float m_run[4], l_run[4];
#pragma unroll
    for (int i = 0; i < 4; i++) { m_run[i] = -1e30f; l_run[i] = 0.0f; }

    __syncthreads();

    for (int t = 0; t < MCHUNK / MT; ++t) {
        const int m0 = m_start + t * MT;

        // ---- Stage K, C, V, bias tile ----
        for (int i = tid; i < MT * D_ / 4; i += NTHREADS) {
            int e = i * 4, r = e >> 6, c = e & 63;
            *(float4*)(sK + r * KS + c) = *(const float4*)(mk + (m0 + r) * D_ + c);
            *(float4*)(sV + r * VS + c) = *(const float4*)(mv + (m0 + r) * D_ + c);
        }
        for (int i = tid; i < MT * CD_ / 4; i += NTHREADS) {
            int e = i * 4, r = e >> 5, c = e & 31;
            *(float4*)(sCk + r * CS + c) = *(const float4*)(mc + (m0 + r) * CD_ + c);
        }
        if (tid < MT) sB[tid] = g_bias[m0 + tid];
        __syncthreads();

        // ---- Scores: 4x4 micro-tile over D (Q·K) then CD (0.5*Ctx·C) ----
        float s[4][4] = {};
#pragma unroll
        for (int kk = 0; kk < D_; kk += 4) {
            float4 qa[4], kb[4];
#pragma unroll
            for (int i = 0; i < 4; i++) qa[i] = *(const float4*)(sQ + (r0 + i) * QS + kk);
#pragma unroll
            for (int j = 0; j < 4; j++) kb[j] = *(const float4*)(sK + (c0 + j) * KS + kk);
#pragma unroll
            for (int i = 0; i < 4; i++)
#pragma unroll
                for (int j = 0; j < 4; j++) {
                    s[i][j] = fmaf(qa[i].x, kb[j].x, s[i][j]);
                    s[i][j] = fmaf(qa[i].y, kb[j].y, s[i][j]);
                    s[i][j] = fmaf(qa[i].z, kb[j].z, s[i][j]);
                    s[i][j] = fmaf(qa[i].w, kb[j].w, s[i][j]);
                }
        }
#pragma unroll
        for (int kk = 0; kk < CD_; kk += 4) {
            float4 qa[4], kb[4];
#pragma unroll
            for (int i = 0; i < 4; i++) qa[i] = *(const float4*)(sC + (r0 + i) * CS + kk);
#pragma unroll
            for (int j = 0; j < 4; j++) kb[j] = *(const float4*)(sCk + (c0 + j) * CS + kk);
#pragma unroll
            for (int i = 0; i < 4; i++)
#pragma unroll
                for (int j = 0; j < 4; j++) {
                    s[i][j] = fmaf(qa[i].x, kb[j].x, s[i][j]);
                    s[i][j] = fmaf(qa[i].y, kb[j].y, s[i][j]);
                    s[i][j] = fmaf(qa[i].z, kb[j].z, s[i][j]);
                    s[i][j] = fmaf(qa[i].w, kb[j].w, s[i][j]);
                }
        }

        // ---- Bias + online softmax update (row stats across 16 cg lanes) ----
#pragma unroll
        for (int i = 0; i < 4; i++) {
#pragma unroll
            for (int j = 0; j < 4; j++) s[i][j] += sB[c0 + j];

            float mx = fmaxf(fmaxf(s[i][0], s[i][1]), fmaxf(s[i][2], s[i][3]));
#pragma unroll
            for (int off = 8; off >= 1; off >>= 1)
                mx = fmaxf(mx, __shfl_xor_sync(0xffffffffu, mx, off));

            float nm = fmaxf(m_run[i], mx);
            float alpha = __expf(m_run[i] - nm);
            float rs = 0.0f;
#pragma unroll
            for (int j = 0; j < 4; j++) {
                float p = __expf(s[i][j] - nm);
                s[i][j] = p;
                rs += p;
            }
#pragma unroll
            for (int off = 8; off >= 1; off >>= 1)
                rs += __shfl_xor_sync(0xffffffffu, rs, off);

            l_run[i] = l_run[i] * alpha + rs;
            m_run[i] = nm;
#pragma unroll
            for (int j = 0; j < 4; j++) acc[i][j] *= alpha;

            *(float4*)(sP + (r0 + i) * PS + c0) =
                make_float4(s[i][0], s[i][1], s[i][2], s[i][3]);
        }
        __syncthreads();

        // ---- P·V accumulate: rows r0..+3, out dims d0..+3 ----
#pragma unroll 4
        for (int mm = 0; mm < MT; mm += 4) {
            float4 vv[4];
#pragma unroll
            for (int u = 0; u < 4; u++)
                vv[u] = *(const float4*)(sV + (mm + u) * VS + d0);
#pragma unroll
            for (int i = 0; i < 4; i++) {
                float4 pv = *(const float4*)(sP + (r0 + i) * PS + mm);
                float pa[4] = {pv.x, pv.y, pv.z, pv.w};
#pragma unroll
                for (int u = 0; u < 4; u++) {
                    float p = pa[u];
                    acc[i][0] = fmaf(p, vv[u].x, acc[i][0]);
                    acc[i][1] = fmaf(p, vv[u].y, acc[i][1]);
                    acc[i][2] = fmaf(p, vv[u].z, acc[i][2]);
                    acc[i][3] = fmaf(p, vv[u].w, acc[i][3]);
                }
            }
        }
        __syncthreads();   // protect sK/sV/sP before next tile's loads
    }

    // ---- Write split partials ----
#pragma unroll
    for (int i = 0; i < 4; i++) {
        int brow = row0 + r0 + i;
        int pidx = brow * S_ + blockIdx.y;
        *(float4*)(g_pacc + pidx * D_ + d0) =
            make_float4(acc[i][0], acc[i][1], acc[i][2], acc[i][3]);
        if (cg == 0) {
            g_pm[pidx] = m_run[i];
            g_pl[pidx] = l_run[i];
        }
    }
}

// ---------------------------------------------------------------------------
// Kernel 3: combine S split partials per row. One warp per row, 2 dims/lane.
// ---------------------------------------------------------------------------
__global__ void combine_kernel(float* __restrict__ out) {
    int warp = threadIdx.x >> 5;
    int lane = threadIdx.x & 31;
    int row = blockIdx.x * 8 + warp;
    if (row >= B_) return;

    float pm[S_];
    float nm = -1e30f;
#pragma unroll
    for (int s = 0; s < S_; s++) {
        pm[s] = g_pm[row * S_ + s];
        nm = fmaxf(nm, pm[s]);
    }
    float den = 0.0f, n0 = 0.0f, n1 = 0.0f;
#pragma unroll
    for (int s = 0; s < S_; s++) {
        float w = __expf(pm[s] - nm);
        den += w * g_pl[row * S_ + s];
        n0  += w * g_pacc[(row * S_ + s) * D_ + lane];
        n1  += w * g_pacc[(row * S_ + s) * D_ + lane + 32];
    }
    float inv = 1.0f / den;
    out[row * D_ + lane]      = n0 * inv;
    out[row * D_ + lane + 32] = n1 * inv;
}

// ---------------------------------------------------------------------------
// Launch
// ---------------------------------------------------------------------------
extern "C" void kernel_launch(void* const* d_in, const int* in_sizes, int n_in,
                              void* d_out, int out_size) {
    const float* q   = (const float*)d_in[0];  // [B, D]
    const float* ctx = (const float*)d_in[1];  // [B, CD]
    const float* mk  = (const float*)d_in[2];  // [M, D]
    const float* mv  = (const float*)d_in[3];  // [M, D]
    const float* mc  = (const float*)d_in[4];  // [M, CD]
    const float* ts  = (const float*)d_in[5];  // [M]
    const int*   us  = (const int*)d_in[6];    // [M] bool as int32
    float* out = (float*)d_out;

    cudaFuncSetAttribute(flash_kernel,
                         cudaFuncAttributeMaxDynamicSharedMemorySize,
                         SMEM_BYTES);

    bias_kernel<<<M_ / 256, 256>>>(ts, us);
    flash_kernel<<<dim3(B_ / BT, S_), NTHREADS, SMEM_BYTES>>>(q, ctx, mk, mv, mc);
    combine_kernel<<<B_ / 8, 256>>>(out);
}

// round 9
// speedup vs baseline: 1.0020x; 1.0015x over previous
#include <cuda_runtime.h>
#include <math.h>

// Problem constants
#define B_   4096
#define M_   65536
#define D_   64
#define CD_  32

// Tiling
#define S_       8            // M-splits (grid.y)
#define MCHUNK   (M_ / S_)    // 8192 slots per CTA
#define BT       64           // batch rows per CTA
#define MT       64           // slots per inner tile
#define NTHREADS 256

// Padded shared strides (floats) to avoid bank conflicts
#define QS 68
#define CS 36
#define KS 68
#define VS 68
#define PS 68

#define SMEM_FLOATS (BT*QS + BT*CS + MT*KS + MT*CS + MT*VS + BT*PS + MT)
#define SMEM_BYTES  (SMEM_FLOATS * 4)

// Scratch (no cudaMalloc allowed): bias + split partials
__device__ float g_bias[M_];
__device__ float g_pacc[B_ * S_ * D_];
__device__ float g_pm[B_ * S_];
__device__ float g_pl[B_ * S_];

// ---------------------------------------------------------------------------
// Kernel 1: per-slot additive bias: 0.3*exp(-0.1*(1-t)) for used slots,
// -1e9 for unused (content scores are O(10), so total stays ~-1e9 and
// exp underflows to exactly 0 after max-subtraction, matching the reference).
// ---------------------------------------------------------------------------
__global__ void bias_kernel(const float* __restrict__ ts,
                            const int* __restrict__ used) {
    int i = blockIdx.x * blockDim.x + threadIdx.x;
    if (i < M_) {
        float b = -1e9f;
        if (used[i] != 0) b = 0.3f * expf(-0.1f * (1.0f - ts[i]));
        g_bias[i] = b;
    }
}

// ---------------------------------------------------------------------------
// Kernel 2: flash-style fused scores + online softmax + P·V over an M-chunk.
// blockIdx.x -> batch tile (64 rows), blockIdx.y -> M split.
// Thread (rg, cg): rg = tid>>4 owns rows rg*4..+3 (both phases),
//                  cg = tid&15 owns score cols cg*4..+3 and out dims cg*4..+3.
// ---------------------------------------------------------------------------
__global__ __launch_bounds__(NTHREADS, 2)
void flash_kernel(const float* __restrict__ q,
                  const float* __restrict__ ctx,
                  const float* __restrict__ mk,
                  const float* __restrict__ mv,
                  const float* __restrict__ mc) {
    extern __shared__ float sm[];
    float* sQ  = sm;                 // [BT][QS]
    float* sC  = sQ  + BT * QS;      // [BT][CS]  (prescaled by 0.5)
    float* sK  = sC  + BT * CS;      // [MT][KS]
    float* sCk = sK  + MT * KS;      // [MT][CS]
    float* sV  = sCk + MT * CS;      // [MT][VS]
    float* sP  = sV  + MT * VS;      // [BT][PS]
    float* sB  = sP  + BT * PS;      // [MT]

    const int tid = threadIdx.x;
    const int rg = tid >> 4;
    const int cg = tid & 15;
    const int r0 = rg * 4;
    const int c0 = cg * 4;
    const int d0 = cg * 4;
    const int row0 = blockIdx.x * BT;
    const int m_start = blockIdx.y * MCHUNK;

    // Stage Q and 0.5*Ctx for this batch tile (reused for all 128 M-tiles)
    for (int i = tid; i < BT * D_ / 4; i += NTHREADS) {
        int e = i * 4, r = e >> 6, c = e & 63;
        *(float4*)(sQ + r * QS + c) = *(const float4*)(q + (row0 + r) * D_ + c);
    }
    for (int i = tid; i < BT * CD_ / 4; i += NTHREADS) {
        int e = i * 4, r = e >> 5, c = e & 31;
        float4 v = *(const float4*)(ctx + (row0 + r) * CD_ + c);
        v.x *= 0.5f; v.y *= 0.5f; v.z *= 0.5f; v.w *= 0.5f;
        *(float4*)(sC + r * CS + c) = v;
    }

    float acc[4][4] = {};
    float m_run[4], l_run[4];
#pragma unroll
    for (int i = 0; i < 4; i++) { m_run[i] = -1e30f; l_run[i] = 0.0f; }

    __syncthreads();

    for (int t = 0; t < MCHUNK / MT; ++t) {
        const int m0 = m_start + t * MT;

        // ---- Stage K, C, V, bias tile ----
        for (int i = tid; i < MT * D_ / 4; i += NTHREADS) {
            int e = i * 4, r = e >> 6, c = e & 63;
            *(float4*)(sK + r * KS + c) = *(const float4*)(mk + (m0 + r) * D_ + c);
            *(float4*)(sV + r * VS + c) = *(const float4*)(mv + (m0 + r) * D_ + c);
        }
        for (int i = tid; i < MT * CD_ / 4; i += NTHREADS) {
            int e = i * 4, r = e >> 5, c = e & 31;
            *(float4*)(sCk + r * CS + c) = *(const float4*)(mc + (m0 + r) * CD_ + c);
        }
        if (tid < MT) sB[tid] = g_bias[m0 + tid];
        __syncthreads();

        // ---- Scores: 4x4 micro-tile over D (Q·K) then CD (0.5*Ctx·C) ----
        float s[4][4] = {};
#pragma unroll
        for (int kk = 0; kk < D_; kk += 4) {
            float4 qa[4], kb[4];
#pragma unroll
            for (int i = 0; i < 4; i++) qa[i] = *(const float4*)(sQ + (r0 + i) * QS + kk);
#pragma unroll
            for (int j = 0; j < 4; j++) kb[j] = *(const float4*)(sK + (c0 + j) * KS + kk);
#pragma unroll
            for (int i = 0; i < 4; i++)
#pragma unroll
                for (int j = 0; j < 4; j++) {
                    s[i][j] = fmaf(qa[i].x, kb[j].x, s[i][j]);
                    s[i][j] = fmaf(qa[i].y, kb[j].y, s[i][j]);
                    s[i][j] = fmaf(qa[i].z, kb[j].z, s[i][j]);
                    s[i][j] = fmaf(qa[i].w, kb[j].w, s[i][j]);
                }
        }
#pragma unroll
        for (int kk = 0; kk < CD_; kk += 4) {
            float4 qa[4], kb[4];
#pragma unroll
            for (int i = 0; i < 4; i++) qa[i] = *(const float4*)(sC + (r0 + i) * CS + kk);
#pragma unroll
            for (int j = 0; j < 4; j++) kb[j] = *(const float4*)(sCk + (c0 + j) * CS + kk);
#pragma unroll
            for (int i = 0; i < 4; i++)
#pragma unroll
                for (int j = 0; j < 4; j++) {
                    s[i][j] = fmaf(qa[i].x, kb[j].x, s[i][j]);
                    s[i][j] = fmaf(qa[i].y, kb[j].y, s[i][j]);
                    s[i][j] = fmaf(qa[i].z, kb[j].z, s[i][j]);
                    s[i][j] = fmaf(qa[i].w, kb[j].w, s[i][j]);
                }
        }

        // ---- Bias + online softmax update (row stats across 16 cg lanes) ----
#pragma unroll
        for (int i = 0; i < 4; i++) {
#pragma unroll
            for (int j = 0; j < 4; j++) s[i][j] += sB[c0 + j];

            float mx = fmaxf(fmaxf(s[i][0], s[i][1]), fmaxf(s[i][2], s[i][3]));
#pragma unroll
            for (int off = 8; off >= 1; off >>= 1)
                mx = fmaxf(mx, __shfl_xor_sync(0xffffffffu, mx, off));

            float nm = fmaxf(m_run[i], mx);
            float alpha = __expf(m_run[i] - nm);
            float rs = 0.0f;
#pragma unroll
            for (int j = 0; j < 4; j++) {
                float p = __expf(s[i][j] - nm);
                s[i][j] = p;
                rs += p;
            }
#pragma unroll
            for (int off = 8; off >= 1; off >>= 1)
                rs += __shfl_xor_sync(0xffffffffu, rs, off);

            l_run[i] = l_run[i] * alpha + rs;
            m_run[i] = nm;
#pragma unroll
            for (int j = 0; j < 4; j++) acc[i][j] *= alpha;

            *(float4*)(sP + (r0 + i) * PS + c0) =
                make_float4(s[i][0], s[i][1], s[i][2], s[i][3]);
        }
        __syncthreads();

        // ---- P·V accumulate: rows r0..+3, out dims d0..+3 ----
#pragma unroll 4
        for (int mm = 0; mm < MT; mm += 4) {
            float4 vv[4];
#pragma unroll
            for (int u = 0; u < 4; u++)
                vv[u] = *(const float4*)(sV + (mm + u) * VS + d0);
#pragma unroll
            for (int i = 0; i < 4; i++) {
                float4 pv = *(const float4*)(sP + (r0 + i) * PS + mm);
                float pa[4] = {pv.x, pv.y, pv.z, pv.w};
#pragma unroll
                for (int u = 0; u < 4; u++) {
                    float p = pa[u];
                    acc[i][0] = fmaf(p, vv[u].x, acc[i][0]);
                    acc[i][1] = fmaf(p, vv[u].y, acc[i][1]);
                    acc[i][2] = fmaf(p, vv[u].z, acc[i][2]);
                    acc[i][3] = fmaf(p, vv[u].w, acc[i][3]);
                }
            }
        }
        __syncthreads();   // protect sK/sV/sP before next tile's loads
    }

    // ---- Write split partials ----
#pragma unroll
    for (int i = 0; i < 4; i++) {
        int brow = row0 + r0 + i;
        int pidx = brow * S_ + blockIdx.y;
        *(float4*)(g_pacc + pidx * D_ + d0) =
            make_float4(acc[i][0], acc[i][1], acc[i][2], acc[i][3]);
        if (cg == 0) {
            g_pm[pidx] = m_run[i];
            g_pl[pidx] = l_run[i];
        }
    }
}

// ---------------------------------------------------------------------------
// Kernel 3: combine S split partials per row. One warp per row, 2 dims/lane.
// ---------------------------------------------------------------------------
__global__ void combine_kernel(float* __restrict__ out) {
    int warp = threadIdx.x >> 5;
    int lane = threadIdx.x & 31;
    int row = blockIdx.x * 8 + warp;
    if (row >= B_) return;

    float pm[S_];
    float nm = -1e30f;
#pragma unroll
    for (int s = 0; s < S_; s++) {
        pm[s] = g_pm[row * S_ + s];
        nm = fmaxf(nm, pm[s]);
    }
    float den = 0.0f, n0 = 0.0f, n1 = 0.0f;
#pragma unroll
    for (int s = 0; s < S_; s++) {
        float w = __expf(pm[s] - nm);
        den += w * g_pl[row * S_ + s];
        n0  += w * g_pacc[(row * S_ + s) * D_ + lane];
        n1  += w * g_pacc[(row * S_ + s) * D_ + lane + 32];
    }
    float inv = 1.0f / den;
    out[row * D_ + lane]      = n0 * inv;
    out[row * D_ + lane + 32] = n1 * inv;
}

// ---------------------------------------------------------------------------
// Launch
// ---------------------------------------------------------------------------
extern "C" void kernel_launch(void* const* d_in, const int* in_sizes, int n_in,
                              void* d_out, int out_size) {
    const float* q   = (const float*)d_in[0];  // [B, D]
    const float* ctx = (const float*)d_in[1];  // [B, CD]
    const float* mk  = (const float*)d_in[2];  // [M, D]
    const float* mv  = (const float*)d_in[3];  // [M, D]
    const float* mc  = (const float*)d_in[4];  // [M, CD]
    const float* ts  = (const float*)d_in[5];  // [M]
    const int*   us  = (const int*)d_in[6];    // [M] bool as int32
    float* out = (float*)d_out;

    cudaFuncSetAttribute(flash_kernel,
                         cudaFuncAttributeMaxDynamicSharedMemorySize,
                         SMEM_BYTES);

    bias_kernel<<<M_ / 256, 256>>>(ts, us);
    flash_kernel<<<dim3(B_ / BT, S_), NTHREADS, SMEM_BYTES>>>(q, ctx, mk, mv, mc);
    combine_kernel<<<B_ / 8, 256>>>(out);
}

// round 11
// speedup vs baseline: 6.0757x; 6.0634x over previous
#include <cuda_runtime.h>
#include <cuda_bf16.h>
#include <math.h>

#define B_   4096
#define M_   65536
#define D_   64
#define CD_  32
#define S_   32
#define MCHUNK (M_/S_)        // 2048 slots per CTA
#define MT    64              // slots per inner tile
#define NTILES (MCHUNK/MT)    // 32
#define BT    128             // batch rows per CTA (8 warps x 16)
#define NTHREADS 256

// smem double buffer layout (byte offsets within one buffer)
#define oKH   0u
#define oKL   8192u
#define oVH   16384u
#define oVL   24576u
#define oCH   32768u
#define oCL   40960u
#define oBias 49152u
#define BUFSZ 50176u
#define SMEM_TOTAL (2u*BUFSZ)

// ---------------- device scratch (no cudaMalloc allowed) -------------------
__device__ __nv_bfloat16 g_kh[(size_t)M_*D_],  g_kl[(size_t)M_*D_];
__device__ __nv_bfloat16 g_vh[(size_t)M_*D_],  g_vl[(size_t)M_*D_];
__device__ __nv_bfloat16 g_ch[(size_t)M_*CD_], g_cl[(size_t)M_*CD_];
__device__ float g_bias[M_];
__device__ float g_pout[(size_t)B_*S_*D_];
__device__ float g_pden[(size_t)B_*S_];

// ---------------- helpers ---------------------------------------------------
__device__ __forceinline__ unsigned smem_u32(const void* p) {
    unsigned a;
    asm("{ .reg .u64 t; cvta.to.shared.u64 t, %1; cvt.u32.u64 %0, t; }"
        : "=r"(a) : "l"(p));
    return a;
}
__device__ __forceinline__ unsigned swz(unsigned o) { return o ^ ((o >> 3) & 0x70); }

__device__ __forceinline__ void cp16(unsigned d, const void* s) {
    asm volatile("cp.async.cg.shared.global [%0], [%1], 16;" :: "r"(d), "l"(s));
}
#define CP_COMMIT() asm volatile("cp.async.commit_group;" ::: "memory")
#define CP_WAIT0()  asm volatile("cp.async.wait_group 0;" ::: "memory")

__device__ __forceinline__ void ldsm_x4(unsigned* r, unsigned a) {
    asm volatile("ldmatrix.sync.aligned.m8n8.x4.shared.b16 {%0,%1,%2,%3}, [%4];"
        : "=r"(r[0]), "=r"(r[1]), "=r"(r[2]), "=r"(r[3]) : "r"(a));
}
__device__ __forceinline__ void ldsm_x4_t(unsigned* r, unsigned a) {
    asm volatile("ldmatrix.sync.aligned.m8n8.x4.trans.shared.b16 {%0,%1,%2,%3}, [%4];"
        : "=r"(r[0]), "=r"(r[1]), "=r"(r[2]), "=r"(r[3]) : "r"(a));
}

// D(16x8,f32) += A(16x16,bf16) * B(16x8,bf16)
__device__ __forceinline__ void mma16816(float* c, const unsigned* a, const unsigned* b) {
    asm volatile("mma.sync.aligned.m16n8k16.row.col.f32.bf16.bf16.f32 "
        "{%0,%1,%2,%3}, {%4,%5,%6,%7}, {%8,%9}, {%0,%1,%2,%3};"
        : "+f"(c[0]), "+f"(c[1]), "+f"(c[2]), "+f"(c[3])
        : "r"(a[0]), "r"(a[1]), "r"(a[2]), "r"(a[3]), "r"(b[0]), "r"(b[1]));
}

// pack (a=low half, b=high half) to bf16x2 hi word + bf16x2 residual word
__device__ __forceinline__ void pack_hl(float a, float b, unsigned& h, unsigned& l) {
    asm("cvt.rn.bf16x2.f32 %0, %1, %2;" : "=r"(h) : "f"(b), "f"(a));
    float ha = __uint_as_float(h << 16);
    float hb = __uint_as_float(h & 0xffff0000u);
    asm("cvt.rn.bf16x2.f32 %0, %1, %2;" : "=r"(l) : "f"(b - hb), "f"(a - ha));
}

// ---------------- prep: hi/lo splits + bias ---------------------------------
__global__ void prep_kernel(const float* __restrict__ mk,
                            const float* __restrict__ mv,
                            const float* __restrict__ mc,
                            const float* __restrict__ ts,
                            const int* __restrict__ used) {
    size_t i = (size_t)blockIdx.x * 256 + threadIdx.x;
    if (i < (size_t)M_ * D_) {
        float x = mk[i];
        __nv_bfloat16 h = __float2bfloat16(x);
        g_kh[i] = h;
        g_kl[i] = __float2bfloat16(x - __bfloat162float(h));
        float y = mv[i];
        __nv_bfloat16 hv = __float2bfloat16(y);
        g_vh[i] = hv;
        g_vl[i] = __float2bfloat16(y - __bfloat162float(hv));
    }
    if (i < (size_t)M_ * CD_) {
        float x = mc[i];
        __nv_bfloat16 h = __float2bfloat16(x);
        g_ch[i] = h;
        g_cl[i] = __float2bfloat16(x - __bfloat162float(h));
    }
    if (i < M_) {
        float b = -1e9f;
        if (used[i] != 0) b = 0.3f * expf(-0.1f * (1.0f - ts[i]));
        g_bias[i] = b;
    }
}

// ---------------- tile stage (cp.async into one buffer) ---------------------
__device__ __forceinline__ void stage_tile(int m0, unsigned dst, int tid) {
    for (int idx = tid; idx < 2576; idx += NTHREADS) {
        const char* src;
        unsigned d;
        if (idx < 1024) {            // K hi/lo: 64 rows x 128B
            int t = idx >> 9, k = idx & 511, r = k >> 3, c = k & 7;
            src = (const char*)((t ? g_kl : g_kh) + (size_t)(m0 + r) * D_ + c * 8);
            d = dst + (t ? oKL : oKH) + swz((unsigned)(r * 128 + c * 16));
        } else if (idx < 2048) {     // V hi/lo
            int t = (idx - 1024) >> 9, k = idx & 511, r = k >> 3, c = k & 7;
            src = (const char*)((t ? g_vl : g_vh) + (size_t)(m0 + r) * D_ + c * 8);
            d = dst + (t ? oVL : oVH) + swz((unsigned)(r * 128 + c * 16));
        } else if (idx < 2560) {     // C hi/lo: 64 rows x 64B payload, 128B stride
            int t = (idx - 2048) >> 8, k = idx & 255, r = k >> 2, c = k & 3;
            src = (const char*)((t ? g_cl : g_ch) + (size_t)(m0 + r) * CD_ + c * 8);
            d = dst + (t ? oCL : oCH) + swz((unsigned)(r * 128 + c * 16));
        } else {                     // bias: 64 floats
            int k = idx - 2560;
            src = (const char*)(g_bias + m0 + k * 4);
            d = dst + oBias + (unsigned)(k * 16);
        }
        cp16(d, src);
    }
    CP_COMMIT();
}

// ---------------- main attention kernel -------------------------------------
#define QK_PASS(Aq, kOff) do { \
    _Pragma("unroll") for (int kbp = 0; kbp < 2; kbp++) { \
        _Pragma("unroll") for (int n = 0; n < 8; n++) { \
            unsigned bfr[4]; \
            ldsm_x4(bfr, buf + (kOff) + swz((unsigned)((n * 8 + jj) * 128 + kbp * 64 + ii * 16))); \
            mma16816(sacc[n], (Aq)[2 * kbp],     bfr); \
            mma16816(sacc[n], (Aq)[2 * kbp + 1], bfr + 2); \
        } } } while (0)

#define CX_PASS(Ac, cOff) do { \
    _Pragma("unroll") for (int n = 0; n < 8; n++) { \
        unsigned bfr[4]; \
        ldsm_x4(bfr, buf + (cOff) + swz((unsigned)((n * 8 + jj) * 128 + ii * 16))); \
        mma16816(sacc[n], (Ac)[0], bfr); \
        mma16816(sacc[n], (Ac)[1], bfr + 2); \
    } } while (0)

#define PV_PASS(Ap, vOff) do { \
    _Pragma("unroll") for (int kb = 0; kb < 4; kb++) { \
        _Pragma("unroll") for (int dd = 0; dd < 4; dd++) { \
            unsigned bfr[4]; \
            ldsm_x4_t(bfr, buf + (vOff) + swz((unsigned)((kb * 16 + (ii & 1) * 8 + jj) * 128 + dd * 32 + (ii >> 1) * 16))); \
            mma16816(oacc[2 * dd],     (Ap)[kb], bfr); \
            mma16816(oacc[2 * dd + 1], (Ap)[kb], bfr + 2); \
        } } } while (0)

__global__ __launch_bounds__(NTHREADS, 1)
void attn_kernel(const float* __restrict__ q, const float* __restrict__ ctx) {
    extern __shared__ char smem[];
    const unsigned sbase = smem_u32(smem);
    const int tid = threadIdx.x;
    const int warp = tid >> 5, lane = tid & 31;
    const int g = lane >> 2, tq = lane & 3;
    const int ii = lane >> 3, jj = lane & 7;      // ldmatrix lane decomposition
    const int row0 = blockIdx.x * BT;
    const int split = blockIdx.y;
    const int m_base = split * MCHUNK;
    const int rg = row0 + warp * 16 + g;          // this thread's rows: rg, rg+8

    // ---- A fragments for Q (4 kblocks) and 0.5*ctx (2 kblocks), hi/lo ------
    unsigned qh[4][4], ql[4][4], ch[2][4], cl[2][4];
#pragma unroll
    for (int kb = 0; kb < 4; kb++) {
        int c0 = kb * 16 + 2 * tq;
        const float* q0 = q + (size_t)rg * D_;
        const float* q1 = q + (size_t)(rg + 8) * D_;
        float2 x00 = *(const float2*)(q0 + c0);
        float2 x10 = *(const float2*)(q1 + c0);
        float2 x01 = *(const float2*)(q0 + c0 + 8);
        float2 x11 = *(const float2*)(q1 + c0 + 8);
        pack_hl(x00.x, x00.y, qh[kb][0], ql[kb][0]);
        pack_hl(x10.x, x10.y, qh[kb][1], ql[kb][1]);
        pack_hl(x01.x, x01.y, qh[kb][2], ql[kb][2]);
        pack_hl(x11.x, x11.y, qh[kb][3], ql[kb][3]);
    }
#pragma unroll
    for (int kb = 0; kb < 2; kb++) {
        int c0 = kb * 16 + 2 * tq;
        const float* c0p = ctx + (size_t)rg * CD_;
        const float* c1p = ctx + (size_t)(rg + 8) * CD_;
        float2 x00 = *(const float2*)(c0p + c0);
        float2 x10 = *(const float2*)(c1p + c0);
        float2 x01 = *(const float2*)(c0p + c0 + 8);
        float2 x11 = *(const float2*)(c1p + c0 + 8);
        pack_hl(0.5f * x00.x, 0.5f * x00.y, ch[kb][0], cl[kb][0]);
        pack_hl(0.5f * x10.x, 0.5f * x10.y, ch[kb][1], cl[kb][1]);
        pack_hl(0.5f * x01.x, 0.5f * x01.y, ch[kb][2], cl[kb][2]);
        pack_hl(0.5f * x11.x, 0.5f * x11.y, ch[kb][3], cl[kb][3]);
    }

    float oacc[8][4] = {};
    float dden0 = 0.0f, dden1 = 0.0f;

    stage_tile(m_base, sbase, tid);

    for (int t = 0; t < NTILES; t++) {
        CP_WAIT0();
        __syncthreads();
        if (t + 1 < NTILES)
            stage_tile(m_base + (t + 1) * MT, sbase + (unsigned)((t + 1) & 1) * BUFSZ, tid);

        const unsigned buf = sbase + (unsigned)(t & 1) * BUFSZ;
        const float* sB = (const float*)(smem + (size_t)(t & 1) * BUFSZ + oBias);

        // ---- scores: S = Qh·Kh + Ql·Kh + Qh·Kl + Ch·Ch + Cl·Ch + Ch·Cl -----
        float sacc[8][4] = {};
        QK_PASS(qh, oKH);
        QK_PASS(ql, oKH);
        QK_PASS(qh, oKL);
        CX_PASS(ch, oCH);
        CX_PASS(cl, oCH);
        CX_PASS(ch, oCL);

        // ---- epilogue: P = exp(S + bias); repack accum->A-frags hi/lo ------
        unsigned phi[4][4], plo[4][4];
#pragma unroll
        for (int n = 0; n < 8; n++) {
            float b0 = sB[n * 8 + 2 * tq];
            float b1 = sB[n * 8 + 2 * tq + 1];
            float p0 = __expf(sacc[n][0] + b0);
            float p1 = __expf(sacc[n][1] + b1);
            float p2 = __expf(sacc[n][2] + b0);
            float p3 = __expf(sacc[n][3] + b1);
            dden0 += p0 + p1;
            dden1 += p2 + p3;
            int kb = n >> 1, e = (n & 1) * 2;
            pack_hl(p0, p1, phi[kb][e],     plo[kb][e]);
            pack_hl(p2, p3, phi[kb][e + 1], plo[kb][e + 1]);
        }

        // ---- O += Ph·Vh + Pl·Vh + Ph·Vl ------------------------------------
        PV_PASS(phi, oVH);
        PV_PASS(plo, oVH);
        PV_PASS(phi, oVL);
    }

    // ---- row-sum reduce across quad lanes, write split partials ------------
    dden0 += __shfl_xor_sync(0xffffffffu, dden0, 1);
    dden0 += __shfl_xor_sync(0xffffffffu, dden0, 2);
    dden1 += __shfl_xor_sync(0xffffffffu, dden1, 1);
    dden1 += __shfl_xor_sync(0xffffffffu, dden1, 2);
    if (tq == 0) {
        g_pden[(size_t)rg * S_ + split] = dden0;
        g_pden[(size_t)(rg + 8) * S_ + split] = dden1;
    }
    size_t base0 = ((size_t)rg * S_ + split) * D_;
    size_t base1 = ((size_t)(rg + 8) * S_ + split) * D_;
#pragma unroll
    for (int nd = 0; nd < 8; nd++) {
        *(float2*)(g_pout + base0 + nd * 8 + 2 * tq) = make_float2(oacc[nd][0], oacc[nd][1]);
        *(float2*)(g_pout + base1 + nd * 8 + 2 * tq) = make_float2(oacc[nd][2], oacc[nd][3]);
    }
}

// ---------------- combine: normalize across splits --------------------------
__global__ void combine_kernel(float* __restrict__ out) {
    int b = blockIdx.x;
    int d = threadIdx.x;   // 64
    float num = 0.0f, den = 0.0f;
#pragma unroll
    for (int s = 0; s < S_; s++) {
        num += g_pout[((size_t)b * S_ + s) * D_ + d];
        den += g_pden[(size_t)b * S_ + s];
    }
    out[(size_t)b * D_ + d] = num / den;
}

// ---------------- launch -----------------------------------------------------
extern "C" void kernel_launch(void* const* d_in, const int* in_sizes, int n_in,
                              void* d_out, int out_size) {
    const float* q   = (const float*)d_in[0];
    const float* ctx = (const float*)d_in[1];
    const float* mk  = (const float*)d_in[2];
    const float* mv  = (const float*)d_in[3];
    const float* mc  = (const float*)d_in[4];
    const float* ts  = (const float*)d_in[5];
    const int*   us  = (const int*)d_in[6];
    float* out = (float*)d_out;

    cudaFuncSetAttribute(attn_kernel,
                         cudaFuncAttributeMaxDynamicSharedMemorySize, SMEM_TOTAL);

    prep_kernel<<<(M_ * D_) / 256, 256>>>(mk, mv, mc, ts, us);
    attn_kernel<<<dim3(B_ / BT, S_), NTHREADS, SMEM_TOTAL>>>(q, ctx);
    combine_kernel<<<B_, 64>>>(out);
}

// round 12
// speedup vs baseline: 7.6972x; 1.2669x over previous
#include <cuda_runtime.h>
#include <cuda_bf16.h>
#include <math.h>

#define B_   4096
#define M_   65536
#define D_   64
#define CD_  32
#define S_   32
#define MCHUNK (M_/S_)        // 2048 slots per CTA
#define MT    128             // slots per staged tile (2 x 64 compute halves)
#define NTILES (MCHUNK/MT)    // 16
#define BT    128             // batch rows per CTA (8 warps x 16)
#define NTHREADS 256

// smem buffer layout (byte offsets within one buffer); all tiles 1024-aligned
#define oKH   0u
#define oKL   16384u
#define oVH   32768u
#define oVL   49152u
#define oCH   65536u
#define oCL   81920u
#define oBias 98304u          // 128 floats
#define BUFSZ 99328u          // padded to 1024
#define SMEM_TOTAL (2u*BUFSZ)

// ---------------- device scratch (no cudaMalloc allowed) -------------------
__device__ __nv_bfloat16 g_kh[(size_t)M_*D_],  g_kl[(size_t)M_*D_];
__device__ __nv_bfloat16 g_vh[(size_t)M_*D_],  g_vl[(size_t)M_*D_];
__device__ __nv_bfloat16 g_ch[(size_t)M_*CD_], g_cl[(size_t)M_*CD_];
__device__ float g_bias[M_];
__device__ float g_pout[(size_t)B_*S_*D_];
__device__ float g_pden[(size_t)B_*S_];

// ---------------- helpers ---------------------------------------------------
__device__ __forceinline__ unsigned smem_u32(const void* p) {
    unsigned a;
    asm("{ .reg .u64 t; cvta.to.shared.u64 t, %1; cvt.u32.u64 %0, t; }"
        : "=r"(a) : "l"(p));
    return a;
}
__device__ __forceinline__ unsigned swz(unsigned o) { return o ^ ((o >> 3) & 0x70); }

__device__ __forceinline__ void cp16(unsigned d, const void* s) {
    asm volatile("cp.async.cg.shared.global [%0], [%1], 16;" :: "r"(d), "l"(s));
}
#define CP_COMMIT() asm volatile("cp.async.commit_group;" ::: "memory")
#define CP_WAIT0()  asm volatile("cp.async.wait_group 0;" ::: "memory")

__device__ __forceinline__ void ldsm_x4(unsigned* r, unsigned a) {
    asm volatile("ldmatrix.sync.aligned.m8n8.x4.shared.b16 {%0,%1,%2,%3}, [%4];"
        : "=r"(r[0]), "=r"(r[1]), "=r"(r[2]), "=r"(r[3]) : "r"(a));
}
__device__ __forceinline__ void ldsm_x4_t(unsigned* r, unsigned a) {
    asm volatile("ldmatrix.sync.aligned.m8n8.x4.trans.shared.b16 {%0,%1,%2,%3}, [%4];"
        : "=r"(r[0]), "=r"(r[1]), "=r"(r[2]), "=r"(r[3]) : "r"(a));
}

// D(16x8,f32) += A(16x16,bf16) * B(16x8,bf16)
__device__ __forceinline__ void mma16816(float* c, const unsigned* a, const unsigned* b) {
    asm volatile("mma.sync.aligned.m16n8k16.row.col.f32.bf16.bf16.f32 "
        "{%0,%1,%2,%3}, {%4,%5,%6,%7}, {%8,%9}, {%0,%1,%2,%3};"
        : "+f"(c[0]), "+f"(c[1]), "+f"(c[2]), "+f"(c[3])
        : "r"(a[0]), "r"(a[1]), "r"(a[2]), "r"(a[3]), "r"(b[0]), "r"(b[1]));
}

// pack (a=low half, b=high half) to bf16x2 hi word + bf16x2 residual word
__device__ __forceinline__ void pack_hl(float a, float b, unsigned& h, unsigned& l) {
    asm("cvt.rn.bf16x2.f32 %0, %1, %2;" : "=r"(h) : "f"(b), "f"(a));
    float ha = __uint_as_float(h << 16);
    float hb = __uint_as_float(h & 0xffff0000u);
    asm("cvt.rn.bf16x2.f32 %0, %1, %2;" : "=r"(l) : "f"(b - hb), "f"(a - ha));
}

// ---------------- prep: hi/lo splits + bias ---------------------------------
__global__ void prep_kernel(const float* __restrict__ mk,
                            const float* __restrict__ mv,
                            const float* __restrict__ mc,
                            const float* __restrict__ ts,
                            const int* __restrict__ used) {
    size_t i = (size_t)blockIdx.x * 256 + threadIdx.x;
    if (i < (size_t)M_ * D_) {
        float x = mk[i];
        __nv_bfloat16 h = __float2bfloat16(x);
        g_kh[i] = h;
        g_kl[i] = __float2bfloat16(x - __bfloat162float(h));
        float y = mv[i];
        __nv_bfloat16 hv = __float2bfloat16(y);
        g_vh[i] = hv;
        g_vl[i] = __float2bfloat16(y - __bfloat162float(hv));
    }
    if (i < (size_t)M_ * CD_) {
        float x = mc[i];
        __nv_bfloat16 h = __float2bfloat16(x);
        g_ch[i] = h;
        g_cl[i] = __float2bfloat16(x - __bfloat162float(h));
    }
    if (i < M_) {
        float b = -1e9f;
        if (used[i] != 0) b = 0.3f * expf(-0.1f * (1.0f - ts[i]));
        g_bias[i] = b;
    }
}

// ---------------- tile stage (cp.async, fixed-trip, shift-only math) --------
__device__ __forceinline__ void stage_tile(int m0, unsigned dst, int tid) {
#pragma unroll
    for (int i = 0; i < 8; i++) {      // K hi/lo: 2048 cp16
        int idx = tid + i * 256;
        int t = idx >> 10, r = (idx >> 3) & 127, c = idx & 7;
        const char* src = (const char*)((t ? g_kl : g_kh) + ((size_t)(m0 + r) << 6) + c * 8);
        cp16(dst + (t ? oKL : oKH) + swz((unsigned)(r * 128 + c * 16)), src);
    }
#pragma unroll
    for (int i = 0; i < 8; i++) {      // V hi/lo: 2048 cp16
        int idx = tid + i * 256;
        int t = idx >> 10, r = (idx >> 3) & 127, c = idx & 7;
        const char* src = (const char*)((t ? g_vl : g_vh) + ((size_t)(m0 + r) << 6) + c * 8);
        cp16(dst + (t ? oVL : oVH) + swz((unsigned)(r * 128 + c * 16)), src);
    }
#pragma unroll
    for (int i = 0; i < 4; i++) {      // C hi/lo: 1024 cp16 (64B payload/row)
        int idx = tid + i * 256;
        int t = idx >> 9, r = (idx >> 2) & 127, c = idx & 3;
        const char* src = (const char*)((t ? g_cl : g_ch) + ((size_t)(m0 + r) << 5) + c * 8);
        cp16(dst + (t ? oCL : oCH) + swz((unsigned)(r * 128 + c * 16)), src);
    }
    if (tid < 32)                      // bias: 128 floats
        cp16(dst + oBias + (unsigned)(tid * 16), (const char*)(g_bias + m0 + tid * 4));
    CP_COMMIT();
}

// ---------------- main attention kernel -------------------------------------
__global__ __launch_bounds__(NTHREADS, 1)
void attn_kernel(const float* __restrict__ q, const float* __restrict__ ctx) {
    extern __shared__ char smem[];
    const unsigned sbase = smem_u32(smem);
    const int tid = threadIdx.x;
    const int warp = tid >> 5, lane = tid & 31;
    const int g = lane >> 2, tq = lane & 3;
    const int ii = lane >> 3, jj = lane & 7;      // ldmatrix lane decomposition
    const int row0 = blockIdx.x * BT;
    const int split = blockIdx.y;
    const int m_base = split * MCHUNK;
    const int rg = row0 + warp * 16 + g;          // this thread's rows: rg, rg+8

    // ---- A fragments for Q (4 kblocks) and 0.5*ctx (2 kblocks), hi/lo ------
    unsigned qh[4][4], ql[4][4], ch[2][4], cl[2][4];
#pragma unroll
    for (int kb = 0; kb < 4; kb++) {
        int c0 = kb * 16 + 2 * tq;
        const float* q0 = q + (size_t)rg * D_;
        const float* q1 = q + (size_t)(rg + 8) * D_;
        float2 x00 = *(const float2*)(q0 + c0);
        float2 x10 = *(const float2*)(q1 + c0);
        float2 x01 = *(const float2*)(q0 + c0 + 8);
        float2 x11 = *(const float2*)(q1 + c0 + 8);
        pack_hl(x00.x, x00.y, qh[kb][0], ql[kb][0]);
        pack_hl(x10.x, x10.y, qh[kb][1], ql[kb][1]);
        pack_hl(x01.x, x01.y, qh[kb][2], ql[kb][2]);
        pack_hl(x11.x, x11.y, qh[kb][3], ql[kb][3]);
    }
#pragma unroll
    for (int kb = 0; kb < 2; kb++) {
        int c0 = kb * 16 + 2 * tq;
        const float* c0p = ctx + (size_t)rg * CD_;
        const float* c1p = ctx + (size_t)(rg + 8) * CD_;
        float2 x00 = *(const float2*)(c0p + c0);
        float2 x10 = *(const float2*)(c1p + c0);
        float2 x01 = *(const float2*)(c0p + c0 + 8);
        float2 x11 = *(const float2*)(c1p + c0 + 8);
        pack_hl(0.5f * x00.x, 0.5f * x00.y, ch[kb][0], cl[kb][0]);
        pack_hl(0.5f * x10.x, 0.5f * x10.y, ch[kb][1], cl[kb][1]);
        pack_hl(0.5f * x01.x, 0.5f * x01.y, ch[kb][2], cl[kb][2]);
        pack_hl(0.5f * x11.x, 0.5f * x11.y, ch[kb][3], cl[kb][3]);
    }

    float oacc[8][4] = {};
    float dden0 = 0.0f, dden1 = 0.0f;

    stage_tile(m_base, sbase, tid);

    for (int t = 0; t < NTILES; t++) {
        CP_WAIT0();
        __syncthreads();
        if (t + 1 < NTILES)
            stage_tile(m_base + (t + 1) * MT, sbase + (unsigned)((t + 1) & 1) * BUFSZ, tid);

        const unsigned buf = sbase + (unsigned)(t & 1) * BUFSZ;
        const float* sBt = (const float*)(smem + (size_t)(t & 1) * BUFSZ + oBias);

#pragma unroll
        for (int h = 0; h < 2; h++) {          // two 64-slot halves per tile
            const unsigned hoff = (unsigned)h * 8192u;
            const float* sB = sBt + h * 64;

            // ---- init S accumulators with the bias (column-broadcast) -----
            float sacc[8][4];
#pragma unroll
            for (int n = 0; n < 8; n++) {
                float2 b = *(const float2*)(sB + n * 8 + 2 * tq);
                sacc[n][0] = b.x; sacc[n][1] = b.y;
                sacc[n][2] = b.x; sacc[n][3] = b.y;
            }

            // ---- QK: K-hi fragments feed qh AND ql (4 MMAs/ldsm) ----------
#pragma unroll
            for (int kbp = 0; kbp < 2; kbp++)
#pragma unroll
                for (int n = 0; n < 8; n++) {
                    unsigned bfr[4];
                    ldsm_x4(bfr, buf + oKH + hoff +
                        swz((unsigned)((n * 8 + jj) * 128 + kbp * 64 + ii * 16)));
                    mma16816(sacc[n], qh[2 * kbp],     bfr);
                    mma16816(sacc[n], qh[2 * kbp + 1], bfr + 2);
                    mma16816(sacc[n], ql[2 * kbp],     bfr);
                    mma16816(sacc[n], ql[2 * kbp + 1], bfr + 2);
                }
            // ---- K-lo fragments feed qh only (2 MMAs/ldsm) ----------------
#pragma unroll
            for (int kbp = 0; kbp < 2; kbp++)
#pragma unroll
                for (int n = 0; n < 8; n++) {
                    unsigned bfr[4];
                    ldsm_x4(bfr, buf + oKL + hoff +
                        swz((unsigned)((n * 8 + jj) * 128 + kbp * 64 + ii * 16)));
                    mma16816(sacc[n], qh[2 * kbp],     bfr);
                    mma16816(sacc[n], qh[2 * kbp + 1], bfr + 2);
                }
            // ---- C-hi: ch and cl share fragments; C-lo: ch only -----------
#pragma unroll
            for (int n = 0; n < 8; n++) {
                unsigned bfr[4];
                ldsm_x4(bfr, buf + oCH + hoff +
                    swz((unsigned)((n * 8 + jj) * 128 + ii * 16)));
                mma16816(sacc[n], ch[0], bfr);
                mma16816(sacc[n], ch[1], bfr + 2);
                mma16816(sacc[n], cl[0], bfr);
                mma16816(sacc[n], cl[1], bfr + 2);
            }
#pragma unroll
            for (int n = 0; n < 8; n++) {
                unsigned bfr[4];
                ldsm_x4(bfr, buf + oCL + hoff +
                    swz((unsigned)((n * 8 + jj) * 128 + ii * 16)));
                mma16816(sacc[n], ch[0], bfr);
                mma16816(sacc[n], ch[1], bfr + 2);
            }

            // ---- epilogue: P = exp(S); repack accum->A-frags hi/lo --------
            unsigned phi[4][4], plo[4][4];
#pragma unroll
            for (int n = 0; n < 8; n++) {
                float p0 = __expf(sacc[n][0]);
                float p1 = __expf(sacc[n][1]);
                float p2 = __expf(sacc[n][2]);
                float p3 = __expf(sacc[n][3]);
                dden0 += p0 + p1;
                dden1 += p2 + p3;
                int kb = n >> 1, e = (n & 1) * 2;
                pack_hl(p0, p1, phi[kb][e],     plo[kb][e]);
                pack_hl(p2, p3, phi[kb][e + 1], plo[kb][e + 1]);
            }

            // ---- PV: V-hi fragments feed phi AND plo; V-lo: phi only ------
#pragma unroll
            for (int kb = 0; kb < 4; kb++)
#pragma unroll
                for (int dd = 0; dd < 4; dd++) {
                    unsigned bfr[4];
                    ldsm_x4_t(bfr, buf + oVH + hoff +
                        swz((unsigned)((kb * 16 + (ii & 1) * 8 + jj) * 128 + dd * 32 + (ii >> 1) * 16)));
                    mma16816(oacc[2 * dd],     phi[kb], bfr);
                    mma16816(oacc[2 * dd + 1], phi[kb], bfr + 2);
                    mma16816(oacc[2 * dd],     plo[kb], bfr);
                    mma16816(oacc[2 * dd + 1], plo[kb], bfr + 2);
                }
#pragma unroll
            for (int kb = 0; kb < 4; kb++)
#pragma unroll
                for (int dd = 0; dd < 4; dd++) {
                    unsigned bfr[4];
                    ldsm_x4_t(bfr, buf + oVL + hoff +
                        swz((unsigned)((kb * 16 + (ii & 1) * 8 + jj) * 128 + dd * 32 + (ii >> 1) * 16)));
                    mma16816(oacc[2 * dd],     phi[kb], bfr);
                    mma16816(oacc[2 * dd + 1], phi[kb], bfr + 2);
                }
        }
    }

    // ---- row-sum reduce across quad lanes, write split partials ------------
    dden0 += __shfl_xor_sync(0xffffffffu, dden0, 1);
    dden0 += __shfl_xor_sync(0xffffffffu, dden0, 2);
    dden1 += __shfl_xor_sync(0xffffffffu, dden1, 1);
    dden1 += __shfl_xor_sync(0xffffffffu, dden1, 2);
    if (tq == 0) {
        g_pden[(size_t)rg * S_ + split] = dden0;
        g_pden[(size_t)(rg + 8) * S_ + split] = dden1;
    }
    size_t base0 = ((size_t)rg * S_ + split) * D_;
    size_t base1 = ((size_t)(rg + 8) * S_ + split) * D_;
#pragma unroll
    for (int nd = 0; nd < 8; nd++) {
        *(float2*)(g_pout + base0 + nd * 8 + 2 * tq) = make_float2(oacc[nd][0], oacc[nd][1]);
        *(float2*)(g_pout + base1 + nd * 8 + 2 * tq) = make_float2(oacc[nd][2], oacc[nd][3]);
    }
}

// ---------------- combine: normalize across splits --------------------------
__global__ void combine_kernel(float* __restrict__ out) {
    int b = blockIdx.x;
    int d = threadIdx.x;   // 64
    float num = 0.0f, den = 0.0f;
#pragma unroll
    for (int s = 0; s < S_; s++) {
        num += g_pout[((size_t)b * S_ + s) * D_ + d];
        den += g_pden[(size_t)b * S_ + s];
    }
    out[(size_t)b * D_ + d] = num / den;
}

// ---------------- launch -----------------------------------------------------
extern "C" void kernel_launch(void* const* d_in, const int* in_sizes, int n_in,
                              void* d_out, int out_size) {
    const float* q   = (const float*)d_in[0];
    const float* ctx = (const float*)d_in[1];
    const float* mk  = (const float*)d_in[2];
    const float* mv  = (const float*)d_in[3];
    const float* mc  = (const float*)d_in[4];
    const float* ts  = (const float*)d_in[5];
    const int*   us  = (const int*)d_in[6];
    float* out = (float*)d_out;

    cudaFuncSetAttribute(attn_kernel,
                         cudaFuncAttributeMaxDynamicSharedMemorySize, SMEM_TOTAL);

    prep_kernel<<<(M_ * D_) / 256, 256>>>(mk, mv, mc, ts, us);
    attn_kernel<<<dim3(B_ / BT, S_), NTHREADS, SMEM_TOTAL>>>(q, ctx);
    combine_kernel<<<B_, 64>>>(out);
}

// round 13
// speedup vs baseline: 7.9162x; 1.0285x over previous
#include <cuda_runtime.h>
#include <cuda_bf16.h>
#include <math.h>

#define B_   4096
#define M_   65536
#define D_   64
#define CD_  32
#define S_   32
#define MCHUNK (M_/S_)        // 2048 slots per CTA
#define MT    128             // slots per staged tile (2 x 64 compute halves)
#define NTILES (MCHUNK/MT)    // 16
#define BT    128             // batch rows per CTA (8 warps x 16)
#define NTHREADS 256

// smem buffer layout (byte offsets within one buffer); all tiles 1024-aligned
#define oKH   0u
#define oKL   16384u
#define oVH   32768u
#define oVL   49152u
#define oCH   65536u
#define oCL   81920u
#define oBias 98304u          // 128 floats
#define BUFSZ 99328u          // padded to 1024
#define SMEM_TOTAL (2u*BUFSZ)

// ---------------- device scratch (no cudaMalloc allowed) -------------------
__device__ __nv_bfloat16 g_kh[(size_t)M_*D_],  g_kl[(size_t)M_*D_];
__device__ __nv_bfloat16 g_vh[(size_t)M_*D_],  g_vl[(size_t)M_*D_];
__device__ __nv_bfloat16 g_ch[(size_t)M_*CD_], g_cl[(size_t)M_*CD_];
__device__ float g_bias[M_];
__device__ float g_pout[(size_t)B_*S_*D_];
__device__ float g_pden[(size_t)B_*S_];

// ---------------- helpers ---------------------------------------------------
__device__ __forceinline__ unsigned smem_u32(const void* p) {
    unsigned a;
    asm("{ .reg .u64 t; cvta.to.shared.u64 t, %1; cvt.u32.u64 %0, t; }"
        : "=r"(a) : "l"(p));
    return a;
}
__device__ __forceinline__ unsigned swz(unsigned o) { return o ^ ((o >> 3) & 0x70); }

__device__ __forceinline__ void cp16(unsigned d, const void* s) {
    asm volatile("cp.async.cg.shared.global [%0], [%1], 16;" :: "r"(d), "l"(s));
}
#define CP_COMMIT() asm volatile("cp.async.commit_group;" ::: "memory")
#define CP_WAIT0()  asm volatile("cp.async.wait_group 0;" ::: "memory")

__device__ __forceinline__ void ldsm_x4(unsigned* r, unsigned a) {
    asm volatile("ldmatrix.sync.aligned.m8n8.x4.shared.b16 {%0,%1,%2,%3}, [%4];"
        : "=r"(r[0]), "=r"(r[1]), "=r"(r[2]), "=r"(r[3]) : "r"(a));
}
__device__ __forceinline__ void ldsm_x4_t(unsigned* r, unsigned a) {
    asm volatile("ldmatrix.sync.aligned.m8n8.x4.trans.shared.b16 {%0,%1,%2,%3}, [%4];"
        : "=r"(r[0]), "=r"(r[1]), "=r"(r[2]), "=r"(r[3]) : "r"(a));
}

// D(16x8,f32) += A(16x16,bf16) * B(16x8,bf16)
__device__ __forceinline__ void mma16816(float* c, const unsigned* a, const unsigned* b) {
    asm volatile("mma.sync.aligned.m16n8k16.row.col.f32.bf16.bf16.f32 "
        "{%0,%1,%2,%3}, {%4,%5,%6,%7}, {%8,%9}, {%0,%1,%2,%3};"
        : "+f"(c[0]), "+f"(c[1]), "+f"(c[2]), "+f"(c[3])
        : "r"(a[0]), "r"(a[1]), "r"(a[2]), "r"(a[3]), "r"(b[0]), "r"(b[1]));
}

// pack (a=low half, b=high half) to bf16x2 hi word + bf16x2 residual word
__device__ __forceinline__ void pack_hl(float a, float b, unsigned& h, unsigned& l) {
    asm("cvt.rn.bf16x2.f32 %0, %1, %2;" : "=r"(h) : "f"(b), "f"(a));
    float ha = __uint_as_float(h << 16);
    float hb = __uint_as_float(h & 0xffff0000u);
    asm("cvt.rn.bf16x2.f32 %0, %1, %2;" : "=r"(l) : "f"(b - hb), "f"(a - ha));
}

// ---------------- prep: hi/lo splits + bias (4 elems/thread, vectorized) ----
__global__ void prep_kernel(const float* __restrict__ mk,
                            const float* __restrict__ mv,
                            const float* __restrict__ mc,
                            const float* __restrict__ ts,
                            const int* __restrict__ used) {
    size_t i = (size_t)blockIdx.x * 256 + threadIdx.x;   // group of 4 elems
    if (i < (size_t)M_ * D_ / 4) {
        float4 x = ((const float4*)mk)[i];
        unsigned h0, l0, h1, l1;
        pack_hl(x.x, x.y, h0, l0); pack_hl(x.z, x.w, h1, l1);
        ((uint2*)g_kh)[i] = make_uint2(h0, h1);
        ((uint2*)g_kl)[i] = make_uint2(l0, l1);
        float4 y = ((const float4*)mv)[i];
        pack_hl(y.x, y.y, h0, l0); pack_hl(y.z, y.w, h1, l1);
        ((uint2*)g_vh)[i] = make_uint2(h0, h1);
        ((uint2*)g_vl)[i] = make_uint2(l0, l1);
    }
    if (i < (size_t)M_ * CD_ / 4) {
        float4 x = ((const float4*)mc)[i];
        unsigned h0, l0, h1, l1;
        pack_hl(x.x, x.y, h0, l0); pack_hl(x.z, x.w, h1, l1);
        ((uint2*)g_ch)[i] = make_uint2(h0, h1);
        ((uint2*)g_cl)[i] = make_uint2(l0, l1);
    }
    if (i < M_) {
        float b = -1e9f;
        if (used[i] != 0) b = 0.3f * expf(-0.1f * (1.0f - ts[i]));
        g_bias[i] = b;
    }
}

// ---------------- tile stage (cp.async, fixed-trip, shift-only math) --------
__device__ __forceinline__ void stage_tile(int m0, unsigned dst, int tid) {
#pragma unroll
    for (int i = 0; i < 8; i++) {      // K hi/lo: 2048 cp16
        int idx = tid + i * 256;
        int t = idx >> 10, r = (idx >> 3) & 127, c = idx & 7;
        const char* src = (const char*)((t ? g_kl : g_kh) + ((size_t)(m0 + r) << 6) + c * 8);
        cp16(dst + (t ? oKL : oKH) + swz((unsigned)(r * 128 + c * 16)), src);
    }
#pragma unroll
    for (int i = 0; i < 8; i++) {      // V hi/lo: 2048 cp16
        int idx = tid + i * 256;
        int t = idx >> 10, r = (idx >> 3) & 127, c = idx & 7;
        const char* src = (const char*)((t ? g_vl : g_vh) + ((size_t)(m0 + r) << 6) + c * 8);
        cp16(dst + (t ? oVL : oVH) + swz((unsigned)(r * 128 + c * 16)), src);
    }
#pragma unroll
    for (int i = 0; i < 4; i++) {      // C hi/lo: 1024 cp16 (64B payload/row)
        int idx = tid + i * 256;
        int t = idx >> 9, r = (idx >> 2) & 127, c = idx & 3;
        const char* src = (const char*)((t ? g_cl : g_ch) + ((size_t)(m0 + r) << 5) + c * 8);
        cp16(dst + (t ? oCL : oCH) + swz((unsigned)(r * 128 + c * 16)), src);
    }
    if (tid < 32)                      // bias: 128 floats
        cp16(dst + oBias + (unsigned)(tid * 16), (const char*)(g_bias + m0 + tid * 4));
    CP_COMMIT();
}

// ---------------- main attention kernel -------------------------------------
__global__ __launch_bounds__(NTHREADS, 1)
void attn_kernel(const float* __restrict__ q, const float* __restrict__ ctx) {
    extern __shared__ char smem[];
    const unsigned sbase = smem_u32(smem);
    const int tid = threadIdx.x;
    const int warp = tid >> 5, lane = tid & 31;
    const int g = lane >> 2, tq = lane & 3;
    const int ii = lane >> 3, jj = lane & 7;      // ldmatrix lane decomposition
    const int row0 = blockIdx.x * BT;
    const int split = blockIdx.y;
    const int m_base = split * MCHUNK;
    const int rg = row0 + warp * 16 + g;          // this thread's rows: rg, rg+8

    // hoisted swizzled sub-addresses (per-thread constants)
    const unsigned kbase0 = swz((unsigned)(jj * 128 + ii * 16));        // kbp=0
    const unsigned kbase1 = swz((unsigned)(jj * 128 + 64 + ii * 16));   // kbp=1
    const unsigned vrow   = (unsigned)(((ii & 1) * 8 + jj) * 128 + (ii >> 1) * 16);

    // ---- A fragments for Q (4 kblocks) and 0.5*ctx (2 kblocks), hi/lo ------
    unsigned qh[4][4], ql[4][4], ch[2][4], cl[2][4];
#pragma unroll
    for (int kb = 0; kb < 4; kb++) {
        int c0 = kb * 16 + 2 * tq;
        const float* q0 = q + (size_t)rg * D_;
        const float* q1 = q + (size_t)(rg + 8) * D_;
        float2 x00 = *(const float2*)(q0 + c0);
        float2 x10 = *(const float2*)(q1 + c0);
        float2 x01 = *(const float2*)(q0 + c0 + 8);
        float2 x11 = *(const float2*)(q1 + c0 + 8);
        pack_hl(x00.x, x00.y, qh[kb][0], ql[kb][0]);
        pack_hl(x10.x, x10.y, qh[kb][1], ql[kb][1]);
        pack_hl(x01.x, x01.y, qh[kb][2], ql[kb][2]);
        pack_hl(x11.x, x11.y, qh[kb][3], ql[kb][3]);
    }
#pragma unroll
    for (int kb = 0; kb < 2; kb++) {
        int c0 = kb * 16 + 2 * tq;
        const float* c0p = ctx + (size_t)rg * CD_;
        const float* c1p = ctx + (size_t)(rg + 8) * CD_;
        float2 x00 = *(const float2*)(c0p + c0);
        float2 x10 = *(const float2*)(c1p + c0);
        float2 x01 = *(const float2*)(c0p + c0 + 8);
        float2 x11 = *(const float2*)(c1p + c0 + 8);
        pack_hl(0.5f * x00.x, 0.5f * x00.y, ch[kb][0], cl[kb][0]);
        pack_hl(0.5f * x10.x, 0.5f * x10.y, ch[kb][1], cl[kb][1]);
        pack_hl(0.5f * x01.x, 0.5f * x01.y, ch[kb][2], cl[kb][2]);
        pack_hl(0.5f * x11.x, 0.5f * x11.y, ch[kb][3], cl[kb][3]);
    }

    float oacc[8][4] = {};
    float dden0 = 0.0f, dden1 = 0.0f;

    stage_tile(m_base, sbase, tid);

    for (int t = 0; t < NTILES; t++) {
        CP_WAIT0();
        __syncthreads();
        if (t + 1 < NTILES)
            stage_tile(m_base + (t + 1) * MT, sbase + (unsigned)((t + 1) & 1) * BUFSZ, tid);

        const unsigned buf = sbase + (unsigned)(t & 1) * BUFSZ;
        const float* sBt = (const float*)(smem + (size_t)(t & 1) * BUFSZ + oBias);

        // ================= QK for BOTH halves first ========================
        float sacc[2][8][4];
#pragma unroll
        for (int h = 0; h < 2; h++) {
            const unsigned hoff = (unsigned)h * 8192u;
            const float* sB = sBt + h * 64;

            // init S accumulators with the bias (column-broadcast)
#pragma unroll
            for (int n = 0; n < 8; n++) {
                float2 b = *(const float2*)(sB + n * 8 + 2 * tq);
                sacc[h][n][0] = b.x; sacc[h][n][1] = b.y;
                sacc[h][n][2] = b.x; sacc[h][n][3] = b.y;
            }

            // K-hi fragments feed qh AND ql (4 MMAs/ldsm)
#pragma unroll
            for (int kbp = 0; kbp < 2; kbp++) {
                const unsigned a0 = buf + oKH + hoff + (kbp ? kbase1 : kbase0);
#pragma unroll
                for (int n = 0; n < 8; n++) {
                    unsigned bfr[4];
                    ldsm_x4(bfr, a0 + (unsigned)(n * 1024));
                    mma16816(sacc[h][n], qh[2 * kbp],     bfr);
                    mma16816(sacc[h][n], qh[2 * kbp + 1], bfr + 2);
                    mma16816(sacc[h][n], ql[2 * kbp],     bfr);
                    mma16816(sacc[h][n], ql[2 * kbp + 1], bfr + 2);
                }
            }
            // K-lo fragments feed qh only (2 MMAs/ldsm)
#pragma unroll
            for (int kbp = 0; kbp < 2; kbp++) {
                const unsigned a0 = buf + oKL + hoff + (kbp ? kbase1 : kbase0);
#pragma unroll
                for (int n = 0; n < 8; n++) {
                    unsigned bfr[4];
                    ldsm_x4(bfr, a0 + (unsigned)(n * 1024));
                    mma16816(sacc[h][n], qh[2 * kbp],     bfr);
                    mma16816(sacc[h][n], qh[2 * kbp + 1], bfr + 2);
                }
            }
            // C-hi: ch and cl share fragments; C-lo: ch only
            {
                const unsigned a0 = buf + oCH + hoff + kbase0;
#pragma unroll
                for (int n = 0; n < 8; n++) {
                    unsigned bfr[4];
                    ldsm_x4(bfr, a0 + (unsigned)(n * 1024));
                    mma16816(sacc[h][n], ch[0], bfr);
                    mma16816(sacc[h][n], ch[1], bfr + 2);
                    mma16816(sacc[h][n], cl[0], bfr);
                    mma16816(sacc[h][n], cl[1], bfr + 2);
                }
            }
            {
                const unsigned a0 = buf + oCL + hoff + kbase0;
#pragma unroll
                for (int n = 0; n < 8; n++) {
                    unsigned bfr[4];
                    ldsm_x4(bfr, a0 + (unsigned)(n * 1024));
                    mma16816(sacc[h][n], ch[0], bfr);
                    mma16816(sacc[h][n], ch[1], bfr + 2);
                }
            }
        }

        // ============ epilogue + PV, pipelined across halves ================
#pragma unroll
        for (int h = 0; h < 2; h++) {
            const unsigned hoff = (unsigned)h * 8192u;

            // epilogue: P = exp(S); repack accum->A-frags hi/lo
            unsigned phi[4][4], plo[4][4];
#pragma unroll
            for (int n = 0; n < 8; n++) {
                float p0 = __expf(sacc[h][n][0]);
                float p1 = __expf(sacc[h][n][1]);
                float p2 = __expf(sacc[h][n][2]);
                float p3 = __expf(sacc[h][n][3]);
                dden0 += p0 + p1;
                dden1 += p2 + p3;
                int kb = n >> 1, e = (n & 1) * 2;
                pack_hl(p0, p1, phi[kb][e],     plo[kb][e]);
                pack_hl(p2, p3, phi[kb][e + 1], plo[kb][e + 1]);
            }

            // PV: V-hi fragments feed phi AND plo; V-lo: phi only
#pragma unroll
            for (int dd = 0; dd < 4; dd++) {
                const unsigned aH = buf + oVH + hoff + swz(vrow + (unsigned)(dd * 32));
#pragma unroll
                for (int kb = 0; kb < 4; kb++) {
                    unsigned bfr[4];
                    ldsm_x4_t(bfr, aH + (unsigned)(kb * 2048));
                    mma16816(oacc[2 * dd],     phi[kb], bfr);
                    mma16816(oacc[2 * dd + 1], phi[kb], bfr + 2);
                    mma16816(oacc[2 * dd],     plo[kb], bfr);
                    mma16816(oacc[2 * dd + 1], plo[kb], bfr + 2);
                }
                const unsigned aL = buf + oVL + hoff + swz(vrow + (unsigned)(dd * 32));
#pragma unroll
                for (int kb = 0; kb < 4; kb++) {
                    unsigned bfr[4];
                    ldsm_x4_t(bfr, aL + (unsigned)(kb * 2048));
                    mma16816(oacc[2 * dd],     phi[kb], bfr);
                    mma16816(oacc[2 * dd + 1], phi[kb], bfr + 2);
                }
            }
        }
    }

    // ---- row-sum reduce across quad lanes, write split partials ------------
    dden0 += __shfl_xor_sync(0xffffffffu, dden0, 1);
    dden0 += __shfl_xor_sync(0xffffffffu, dden0, 2);
    dden1 += __shfl_xor_sync(0xffffffffu, dden1, 1);
    dden1 += __shfl_xor_sync(0xffffffffu, dden1, 2);
    if (tq == 0) {
        g_pden[(size_t)rg * S_ + split] = dden0;
        g_pden[(size_t)(rg + 8) * S_ + split] = dden1;
    }
    size_t base0 = ((size_t)rg * S_ + split) * D_;
    size_t base1 = ((size_t)(rg + 8) * S_ + split) * D_;
#pragma unroll
    for (int nd = 0; nd < 8; nd++) {
        *(float2*)(g_pout + base0 + nd * 8 + 2 * tq) = make_float2(oacc[nd][0], oacc[nd][1]);
        *(float2*)(g_pout + base1 + nd * 8 + 2 * tq) = make_float2(oacc[nd][2], oacc[nd][3]);
    }
}

// ---------------- combine: normalize across splits --------------------------
__global__ void combine_kernel(float* __restrict__ out) {
    int b = blockIdx.x;
    int d = threadIdx.x;   // 64
    float num = 0.0f, den = 0.0f;
#pragma unroll
    for (int s = 0; s < S_; s++) {
        num += g_pout[((size_t)b * S_ + s) * D_ + d];
        den += g_pden[(size_t)b * S_ + s];
    }
    out[(size_t)b * D_ + d] = num / den;
}

// ---------------- launch -----------------------------------------------------
extern "C" void kernel_launch(void* const* d_in, const int* in_sizes, int n_in,
                              void* d_out, int out_size) {
    const float* q   = (const float*)d_in[0];
    const float* ctx = (const float*)d_in[1];
    const float* mk  = (const float*)d_in[2];
    const float* mv  = (const float*)d_in[3];
    const float* mc  = (const float*)d_in[4];
    const float* ts  = (const float*)d_in[5];
    const int*   us  = (const int*)d_in[6];
    float* out = (float*)d_out;

    cudaFuncSetAttribute(attn_kernel,
                         cudaFuncAttributeMaxDynamicSharedMemorySize, SMEM_TOTAL);

    prep_kernel<<<(M_ * D_ / 4) / 256, 256>>>(mk, mv, mc, ts, us);
    attn_kernel<<<dim3(B_ / BT, S_), NTHREADS, SMEM_TOTAL>>>(q, ctx);
    combine_kernel<<<B_, 64>>>(out);
}